// round 2
// baseline (speedup 1.0000x reference)
#include <cuda_runtime.h>
#include <cstdint>

#define L_SEQ 1024
#define N_ST  256

// Output layout: concat of (c_all[L,N], y_all[L], GBT_A[L,N,N], GBT_B[L,N])
#define OFF_C  ((size_t)0)
#define OFF_Y  ((size_t)(L_SEQ * N_ST))
#define OFF_A  (OFF_Y + (size_t)L_SEQ)
#define OFF_B  (OFF_A + (size_t)L_SEQ * N_ST * N_ST)

// Per-k coefficient tables for the scan, 3MB, L2-resident.
// [k][0] = g_i = s*r_i/e_i, [k][1] = h_i = 1/e_i, [k][2] = b_i = Bd_i * f_k
// Stored in a permuted order so the scan warp's 6 LDG.128/tick are fully
// coalesced: state j=8l+e maps to position 4l+e (e<4) or 128+4l+(e-4).
__device__ float g_tab[L_SEQ][3][N_ST];

__device__ __forceinline__ int perm_pos(int j) {
    int l = j >> 3, e = j & 7;
    return (e < 4) ? (4 * l + e) : (128 + 4 * l + (e - 4));
}

// ---------------------------------------------------------------------------
// Tables + GBT_B.  Closed form: with alpha_i = 1 - s*r_i^2/e_i,
//   Bd_i = ss * (r_i/e_i) * prod_{j<i} alpha_j   (prefix product per k).
// Handles alpha==0 (k<=126) exactly like the forward recurrence.
// ---------------------------------------------------------------------------
__global__ void __launch_bounds__(N_ST) hippo_tabs(
        const float* __restrict__ f, const float* __restrict__ Bvec,
        float* __restrict__ out) {
    __shared__ float sc[2][N_ST];
    const int k = blockIdx.x, j = threadIdx.x;
    const float ss = 1.0f / (float)(k + 1);
    const float s  = 0.5f * ss;
    const float r  = Bvec[j];
    const float e  = fmaf(s, (float)(j + 1), 1.0f);
    const float h  = 1.0f / e;
    const float g  = s * r * h;
    const float al = fmaf(-r, g, 1.0f);   // alpha_j = 1 - s*r^2/e

    // Inclusive prefix product (Hillis-Steele), then shift for exclusive.
    int pb = 0;
    sc[0][j] = al;
    __syncthreads();
    #pragma unroll
    for (int off = 1; off < N_ST; off <<= 1) {
        float v = sc[pb][j];
        if (j >= off) v *= sc[pb][j - off];
        sc[pb ^ 1][j] = v;
        pb ^= 1;
        __syncthreads();
    }
    const float E  = (j == 0) ? 1.0f : sc[pb][j - 1];
    const float Bd = ss * r * h * E;

    const int p = perm_pos(j);
    g_tab[k][0][p] = g;
    g_tab[k][1][p] = h;
    g_tab[k][2][p] = Bd * f[k];
    out[OFF_B + (size_t)k * N_ST + j] = Bd;
}

// ---------------------------------------------------------------------------
// Fused kernel: block 0 = systolic scan (warp 7), blocks 1..1024 = GBT_A fill.
// The two halves are independent (both depend only on hippo_tabs / inputs),
// so they run concurrently inside one launch.
// ---------------------------------------------------------------------------
__global__ void __launch_bounds__(N_ST) hippo_fused(
        const float* __restrict__ initS, const float* __restrict__ Bvec,
        float* __restrict__ out) {
    if (blockIdx.x != 0) {
        // ---- GBT_A fill: column j of M = P1^{-1} via forward substitution,
        //      Ad = 2M - I.  Coalesced 1KB row stores. ----
        __shared__ float r_s[N_ST], a_s[N_ST];
        const int k = blockIdx.x - 1;
        const int j = threadIdx.x;
        const float ss = 1.0f / (float)(k + 1);
        const float s  = 0.5f * ss;
        const float rj = Bvec[j];
        const float ej = fmaf(s, (float)(j + 1), 1.0f);
        const float inv_ej = 1.0f / ej;
        r_s[j] = rj;
        a_s[j] = s * rj * inv_ej;
        __syncthreads();

        float* outA = out + OFF_A + (size_t)k * (N_ST * N_ST) + j;
        float x = 0.0f, S = 0.0f;
        #pragma unroll 4
        for (int i = 0; i < N_ST; i++) {
            float val;
            if (i < j) {
                val = 0.0f;
            } else if (i == j) {
                x = inv_ej; S = rj * x;
                val = fmaf(2.0f, x, -1.0f);
            } else {
                x = -a_s[i] * S;
                S = fmaf(r_s[i], x, S);
                val = 2.0f * x;
            }
            outA[(size_t)i * N_ST] = val;
        }
        return;
    }

    // ---- Systolic scan on warp 7 (highest wid -> arbiter priority). ----
    if (threadIdx.x < 224) return;
    const int lane = threadIdx.x - 224;
    const int ib = lane * 8;

    float r[8], c[8];
    #pragma unroll
    for (int e = 0; e < 8; e++) {
        r[e] = Bvec[ib + e];
        c[e] = initS[ib + e];
    }

    float* outC = out + OFF_C;
    float* outY = out + OFF_Y;

    const float* tb = &g_tab[0][0][0];
    const int o0 = 4 * lane;        // first 4 states' position
    const int o1 = 128 + 4 * lane;  // last 4 states' position

    // 4-deep register prefetch pipeline (6 float4 per tick slot).
    float4 pf[4][6];
    auto pref = [&](int slot, int t) {
        int kk = t - lane;
        kk = (kk < 0) ? 0 : (kk > L_SEQ - 1 ? L_SEQ - 1 : kk);
        const float* p = tb + (size_t)kk * (3 * N_ST);
        pf[slot][0] = *(const float4*)(p + o0);
        pf[slot][1] = *(const float4*)(p + o1);
        pf[slot][2] = *(const float4*)(p + N_ST + o0);
        pf[slot][3] = *(const float4*)(p + N_ST + o1);
        pf[slot][4] = *(const float4*)(p + 2 * N_ST + o0);
        pf[slot][5] = *(const float4*)(p + 2 * N_ST + o1);
    };
    #pragma unroll
    for (int u = 0; u < 4; u++) pref(u, u);

    float V = 0.0f, ys = 0.0f;
    for (int t0 = 0; t0 < 1056; t0 += 4) {       // 1056 >= L_SEQ + 31
        #pragma unroll
        for (int u = 0; u < 4; u++) {
            const int t = t0 + u;
            float Vin = __shfl_up_sync(0xffffffffu, V, 1);
            float yin = __shfl_up_sync(0xffffffffu, ys, 1);
            if (lane == 0) { Vin = 0.0f; yin = 0.0f; }
            const int k = t - lane;
            if ((unsigned)k < (unsigned)L_SEQ) {
                float G[8], H[8], Bv[8];
                G[0]=pf[u][0].x; G[1]=pf[u][0].y; G[2]=pf[u][0].z; G[3]=pf[u][0].w;
                G[4]=pf[u][1].x; G[5]=pf[u][1].y; G[6]=pf[u][1].z; G[7]=pf[u][1].w;
                H[0]=pf[u][2].x; H[1]=pf[u][2].y; H[2]=pf[u][2].z; H[3]=pf[u][2].w;
                H[4]=pf[u][3].x; H[5]=pf[u][3].y; H[6]=pf[u][3].z; H[7]=pf[u][3].w;
                Bv[0]=pf[u][4].x; Bv[1]=pf[u][4].y; Bv[2]=pf[u][4].z; Bv[3]=pf[u][4].w;
                Bv[4]=pf[u][5].x; Bv[5]=pf[u][5].y; Bv[6]=pf[u][5].z; Bv[7]=pf[u][5].w;

                V = Vin;
                float cn[8];
                #pragma unroll
                for (int e = 0; e < 8; e++) {
                    // z_e = h*c - g*V_{e-1};  V_e = alpha*V_{e-1} + r*h*c
                    // (1-FMA critical path through V; z off-chain)
                    float hc  = H[e] * c[e];
                    float al  = fmaf(-r[e], G[e], 1.0f);
                    float z   = fmaf(-G[e], V, hc);
                    float gam = r[e] * hc;
                    cn[e] = fmaf(2.0f, z, Bv[e] - c[e]);
                    V = fmaf(al, V, gam);
                }
                float s01 = cn[0] + cn[1], s23 = cn[2] + cn[3];
                float s45 = cn[4] + cn[5], s67 = cn[6] + cn[7];
                ys = yin + ((s01 + s23) + (s45 + s67));
                #pragma unroll
                for (int e = 0; e < 8; e++) c[e] = cn[e];

                float4* pc = (float4*)(outC + (size_t)k * N_ST + ib);
                pc[0] = make_float4(cn[0], cn[1], cn[2], cn[3]);
                pc[1] = make_float4(cn[4], cn[5], cn[6], cn[7]);
                if (lane == 31) outY[k] = ys;
            } else {
                V = 0.0f; ys = 0.0f;
            }
            pref(u, t + 4);
        }
    }
}

// ---------------------------------------------------------------------------
extern "C" void kernel_launch(void* const* d_in, const int* in_sizes, int n_in,
                              void* d_out, int out_size) {
    const float* f    = (const float*)d_in[0];  // (L,1)
    const float* init = (const float*)d_in[1];  // (N,1)
    // d_in[2] = A (unused: closed form), d_in[3] = B (= r vector)
    const float* B    = (const float*)d_in[3];
    float* out = (float*)d_out;

    hippo_tabs<<<L_SEQ, N_ST>>>(f, B, out);
    hippo_fused<<<L_SEQ + 1, N_ST>>>(init, B, out);
}